// round 13
// baseline (speedup 1.0000x reference)
#include <cuda_runtime.h>
#include <math.h>

#define SLEN 4096
#define EDIM 256
#define HDIM 256
#define TAGS 32
#define NEGV (-10000.0f)
#define CL 8            // CTAs per cluster (one cluster per direction)
#define STARTTAG 30
#define STOPTAG  31

// ---------------- scratch (device globals; no allocation allowed) ----------------
__device__ float g_xg[2][SLEN][4 * HDIM];           // 32 MB : precomputed input gates
__device__ __align__(16) float g_hs[2][SLEN][HDIM]; // 8 MB  : hidden states
__device__ float g_feats[SLEN][TAGS];               // 512 KB

// packed fp32x2 FMA (Blackwell FFMA2): d = a*b + c elementwise on float2
__device__ __forceinline__ float2 ffma2(float2 a, float2 b, float2 c) {
    float2 d;
    asm("fma.rn.f32x2 %0, %1, %2, %3;"
        : "=l"(*reinterpret_cast<unsigned long long*>(&d))
        : "l"(*reinterpret_cast<unsigned long long*>(&a)),
          "l"(*reinterpret_cast<unsigned long long*>(&b)),
          "l"(*reinterpret_cast<unsigned long long*>(&c)));
    return d;
}

// fast sigmoid/tanh via MUFU (__expf rel err ~1e-7: safe for argmax margins)
__device__ __forceinline__ float fast_sigmoid(float x) {
    float e = __expf(-x);
    return __fdividef(1.0f, 1.0f + e);
}
__device__ __forceinline__ float fast_tanh(float x) {
    float e = __expf(-2.0f * x);
    return __fdividef(1.0f - e, 1.0f + e);
}

// ---------------- K1: xg[d][t][r] = emb[sent_d(t)] . w_ih_d[r] + b_d[r] ----------
__global__ void k1_xg(const int* __restrict__ sent,
                      const float* __restrict__ embedding,
                      const float* __restrict__ w_ih_f, const float* __restrict__ b_f,
                      const float* __restrict__ w_ih_b, const float* __restrict__ b_b)
{
    __shared__ __align__(16) float embs[16][EDIM];
    const int d  = blockIdx.z;
    const int t0 = blockIdx.x * 16;
    const int n  = blockIdx.y * 256 + threadIdx.x;   // gate row 0..1023

    for (int tt = 0; tt < 16; tt++) {
        int pos  = t0 + tt;
        int spos = d ? (SLEN - 1 - pos) : pos;
        int tok  = sent[spos];
        embs[tt][threadIdx.x] = embedding[(size_t)tok * EDIM + threadIdx.x];
    }
    __syncthreads();

    const float* W = d ? w_ih_b : w_ih_f;
    const float* B = d ? b_b    : b_f;
    float2 acc[16];
    float bias = B[n];
#pragma unroll
    for (int tt = 0; tt < 16; tt++) acc[tt] = make_float2(bias, 0.0f);

    const float4* Wr = (const float4*)(W + (size_t)n * EDIM);
#pragma unroll 4
    for (int e4 = 0; e4 < EDIM / 4; e4++) {
        float4 w4 = __ldg(&Wr[e4]);
        float2 wA = make_float2(w4.x, w4.y);
        float2 wB = make_float2(w4.z, w4.w);
#pragma unroll
        for (int tt = 0; tt < 16; tt++) {
            float4 ev = *(const float4*)&embs[tt][e4 * 4];
            acc[tt] = ffma2(wA, make_float2(ev.x, ev.y), acc[tt]);
            acc[tt] = ffma2(wB, make_float2(ev.z, ev.w), acc[tt]);
        }
    }
#pragma unroll
    for (int tt = 0; tt < 16; tt++) g_xg[d][t0 + tt][n] = acc[tt].x + acc[tt].y;
}

// ---------------- K2: clustered bidirectional LSTM recurrence --------------------
// Grid = 16 CTAs = 2 clusters of 8 (one per direction), 256 thr/CTA.
// CTA rank owns j in [rank*32, rank*32+32). Warp w owns jl in [4w, 4w+4).
// Exchange (AGGREGATED): each warp's lane 0 STSes its 4 h into the CTA's own
// 128 B slice of hbuf; __syncthreads; fence.proxy.async; threads 0..6 each
// issue ONE cp.async.bulk (128 B) of the slice to one peer CTA, carrying
// mbarrier::complete_tx. Receiver absorbs 7 bulk-tx (was 64 st.async msgs);
// expect_tx = 7*128 = 896 (own slice arrives via local STS, ordered by BARs).
// Two alternating mbarriers; 4-deep h ring keeps WAR safe. Warp 0 is the only
// mbarrier waiter; __syncthreads broadcasts completion.
__global__ void __launch_bounds__(256, 1) __cluster_dims__(CL, 1, 1)
k2_lstm(const float* __restrict__ h0, const float* __restrict__ c0,
        const float* __restrict__ w_hh_f, const float* __restrict__ w_hh_b)
{
    __shared__ __align__(16) float hbuf[4][HDIM];   // 4-deep h ring
    __shared__ __align__(8) unsigned long long mbar[2];

    const int d = blockIdx.x >> 3;                  // cluster id = direction
    unsigned crank;
    asm("mov.u32 %0, %%cluster_ctarank;" : "=r"(crank));
    const int tid  = threadIdx.x;
    const int w    = tid >> 5;
    const int l    = tid & 31;
    const int a    = l >> 3;                        // j slot within warp
    const int gate = (l >> 1) & 3;                  // i,f,g,o
    const int half = l & 1;                         // column half (interleaved)
    const int jl   = w * 4 + a;                     // 0..31
    const int j    = (int)crank * 32 + jl;          // global h index
    const int j0   = (int)crank * 32 + w * 4;       // warp's first j
    const int grow = gate * HDIM + j;               // gate row in [0,1024)

    const float* W = d ? w_hh_b : w_hh_f;
    float4 wr[32];                                  // 128 weights / thread
#pragma unroll
    for (int m = 0; m < 32; m++)
        wr[m] = *(const float4*)(W + (size_t)grow * HDIM + (size_t)(m * 2 + half) * 4);

    unsigned hb = (unsigned)__cvta_generic_to_shared(&hbuf[0][0]);
    unsigned mb = (unsigned)__cvta_generic_to_shared(&mbar[0]);
    // thread tid < 7 sends the slice to peer CTA (skipping self)
    unsigned peer = ((unsigned)tid < crank) ? (unsigned)tid : (unsigned)tid + 1u;
    if (peer >= CL) peer = 0;                       // clamp for tid >= 7 (unused)
    unsigned p_h, p_m;
    asm("mapa.shared::cluster.u32 %0, %1, %2;" : "=r"(p_h) : "r"(hb), "r"(peer));
    asm("mapa.shared::cluster.u32 %0, %1, %2;" : "=r"(p_m) : "r"(mb), "r"(peer));

    if (tid == 0) {
        asm volatile("mbarrier.init.shared.b64 [%0], %1;" :: "r"(mb),     "r"(1) : "memory");
        asm volatile("mbarrier.init.shared.b64 [%0], %1;" :: "r"(mb + 8), "r"(1) : "memory");
        // pre-post: h_1 arrives on mbar[1], h_2 on mbar[0]; 896 B each (7 peers)
        asm volatile("mbarrier.arrive.expect_tx.shared.b64 _, [%0], %1;"
                     :: "r"(mb + 8), "r"((CL - 1) * 128) : "memory");
        asm volatile("mbarrier.arrive.expect_tx.shared.b64 _, [%0], %1;"
                     :: "r"(mb),     "r"((CL - 1) * 128) : "memory");
    }
    hbuf[0][tid] = h0[d * HDIM + tid];              // step 1 reads hbuf[0] = h0
    __syncthreads();
    // all CTAs' mbarrier init done before any bulk copy can target them
    asm volatile("barrier.cluster.arrive.aligned;" ::: "memory");
    asm volatile("barrier.cluster.wait.aligned;"   ::: "memory");

    const bool prod = ((l & 7) == 0);               // lanes 0,8,16,24: own a j
    float cst = c0[d * HDIM + j];                   // used only on prod lanes

    for (int s = 1; s <= SLEN; s++) {
        const int t = s - 1;
        // xg prefetch: issued before the wait, overlaps the mbarrier sleep
        float xw = __ldg(&g_xg[d][t][grow]);

        if (s > 1) {                                // wait h_{s-1} on mbar[(s-1)&1]
            if (w == 0) {                           // ONE warp on the mbarrier word
                unsigned mbw = mb + (unsigned)((s - 1) & 1) * 8u;
                unsigned par = (unsigned)(((s - 2) >> 1) & 1);
                unsigned done;
                asm volatile(
                    "{\n\t.reg .pred p;\n\t"
                    "mbarrier.try_wait.parity.acquire.cluster.shared::cta.b64 p, [%1], %2, 0x989680;\n\t"
                    "selp.b32 %0, 1, 0, p;\n\t}"
                    : "=r"(done) : "r"(mbw), "r"(par) : "memory");
                while (!done) {
                    asm volatile(
                        "{\n\t.reg .pred p;\n\t"
                        "mbarrier.try_wait.parity.acquire.cluster.shared::cta.b64 p, [%1], %2, 0x989680;\n\t"
                        "selp.b32 %0, 1, 0, p;\n\t}"
                        : "=r"(done) : "r"(mbw), "r"(par) : "memory");
                }
                // this barrier's next phase handles h_{s+1}: re-arm it now
                if (l == 0 && s + 1 <= SLEN)
                    asm volatile("mbarrier.arrive.expect_tx.shared.b64 _, [%0], %1;"
                                 :: "r"(mbw), "r"((CL - 1) * 128) : "memory");
            }
            __syncthreads();                        // broadcast completion + ordering
        }

        const float* hsm = &hbuf[(s - 1) & 3][0];
        float2 acc[4];
#pragma unroll
        for (int k = 0; k < 4; k++) acc[k] = make_float2(0.0f, 0.0f);
#pragma unroll
        for (int m = 0; m < 32; m++) {
            float4 h4 = *(const float4*)(hsm + (m * 2 + half) * 4);
            float4 w4 = wr[m];
            float2 ac = acc[m & 3];
            ac = ffma2(make_float2(w4.x, w4.y), make_float2(h4.x, h4.y), ac);
            ac = ffma2(make_float2(w4.z, w4.w), make_float2(h4.z, h4.w), ac);
            acc[m & 3] = ac;
        }
        float accS = ((acc[0].x + acc[0].y) + (acc[1].x + acc[1].y))
                   + ((acc[2].x + acc[2].y) + (acc[3].x + acc[3].y));
        accS += __shfl_xor_sync(0xffffffffu, accS, 1);   // combine halves

        float av  = accS + xw;
        float val = (gate == 2) ? fast_tanh(av) : fast_sigmoid(av);

        const int base = l & 24;                    // lane group of this j
        float iv = __shfl_sync(0xffffffffu, val, base + 0);
        float fv = __shfl_sync(0xffffffffu, val, base + 2);
        float gv = __shfl_sync(0xffffffffu, val, base + 4);
        float ov = __shfl_sync(0xffffffffu, val, base + 6);

        float hv = 0.0f;
        if (prod) {
            cst = fmaf(fv, cst, iv * gv);
            hv  = ov * fast_tanh(cst);
        }
        // gather the warp's 4 h-values to lane 0
        float h0v = __shfl_sync(0xffffffffu, hv, 0);
        float h1v = __shfl_sync(0xffffffffu, hv, 8);
        float h2v = __shfl_sync(0xffffffffu, hv, 16);
        float h3v = __shfl_sync(0xffffffffu, hv, 24);

        if (l == 0) {
            // stage own slice locally (generic-proxy STS)
            *(float4*)&hbuf[s & 3][j0] = make_float4(h0v, h1v, h2v, h3v);
            __stcg((float4*)&g_hs[d][t][j0], make_float4(h0v, h1v, h2v, h3v));
        }
        __syncthreads();                            // all 8 warps' STS complete

        if (tid < CL - 1) {                         // 7 threads, one bulk per peer
            asm volatile("fence.proxy.async.shared::cta;" ::: "memory");
            unsigned dsto = (unsigned)(((s & 3) * HDIM + (int)crank * 32) * 4);
            unsigned mdst = p_m + (unsigned)((s & 1) * 8);
            asm volatile(
                "cp.async.bulk.shared::cluster.shared::cta.mbarrier::complete_tx::bytes "
                "[%0], [%1], %2, [%3];"
                :: "r"(p_h + dsto), "r"(hb + dsto), "r"(128u), "r"(mdst) : "memory");
        }
    }

    // no CTA may exit while peers still write into its SMEM
    asm volatile("barrier.cluster.arrive.aligned;" ::: "memory");
    asm volatile("barrier.cluster.wait.aligned;"   ::: "memory");
}

// ---------------- K3: feats[t] = [hs_f[t], hs_b[S-1-t]] @ lin_w^T + lin_b --------
__global__ void k3_feats(const float* __restrict__ lin_w, const float* __restrict__ lin_b)
{
    __shared__ __align__(16) float cat[2 * HDIM];
    const int t   = blockIdx.x;
    const int tid = threadIdx.x;                // 256
    cat[tid]        = g_hs[0][t][tid];
    cat[HDIM + tid] = g_hs[1][SLEN - 1 - t][tid];
    __syncthreads();

    const int n = tid >> 3, seg = tid & 7;
    const float* w  = lin_w + (size_t)n * 2 * HDIM + seg * 64;
    const float* cc = cat + seg * 64;
    float s = 0.0f;
#pragma unroll 16
    for (int k = 0; k < 64; k++) s = fmaf(w[k], cc[k], s);
    s += __shfl_xor_sync(0xffffffffu, s, 1);
    s += __shfl_xor_sync(0xffffffffu, s, 2);
    s += __shfl_xor_sync(0xffffffffu, s, 4);
    if (seg == 0) g_feats[t][n] = s + lin_b[n];
}

// ---------------- K4: single-warp Viterbi + backtrack (bps in SMEM) --------------
__global__ void __launch_bounds__(32, 1) k4_viterbi(
    const float* __restrict__ trans, float* __restrict__ out, int out_size)
{
    extern __shared__ unsigned char bps[];      // SLEN*TAGS bytes = 128 KB
    const int lane = threadIdx.x;

    float trn[TAGS];
#pragma unroll
    for (int p = 0; p < TAGS; p++) trn[p] = __ldg(&trans[lane * TAGS + p]);
    const float stop_tr = __ldg(&trans[STOPTAG * TAGS + lane]);

    float fv  = (lane == STARTTAG) ? 0.0f : NEGV;
    float ftc = g_feats[0][lane];
    float ftn = g_feats[1][lane];

    for (int t = 0; t < SLEN; t++) {
        float v[TAGS];
        int   bi[TAGS];
#pragma unroll
        for (int p = 0; p < TAGS; p++) {
            v[p]  = __shfl_sync(0xffffffffu, fv, p) + trn[p];
            bi[p] = p;
        }
        // first-max tree: strict > keeps the lower index on ties (== jnp.argmax)
#pragma unroll
        for (int s = 1; s < TAGS; s <<= 1) {
#pragma unroll
            for (int k = 0; k < TAGS; k += 2 * s) {
                if (v[k + s] > v[k]) { v[k] = v[k + s]; bi[k] = bi[k + s]; }
            }
        }
        bps[t * TAGS + lane] = (unsigned char)bi[0];
        fv  = v[0] + ftc;
        ftc = ftn;
        ftn = (t + 2 < SLEN) ? g_feats[t + 2][lane] : 0.0f;
    }

    float v = fv + stop_tr;
    int   b = lane;
#pragma unroll
    for (int ofs = 16; ofs > 0; ofs >>= 1) {
        float ov = __shfl_down_sync(0xffffffffu, v, ofs);
        int   oi = __shfl_down_sync(0xffffffffu, b, ofs);
        if (ov > v || (ov == v && oi < b)) { v = ov; b = oi; }
    }

    if (lane == 0) {
        const int off = (out_size > SLEN) ? 1 : 0;
        if (off) out[0] = v;
        int cur = b;
        for (int t = SLEN - 1; t >= 0; t--) {
            int idx = off + t;
            if (idx < out_size) out[idx] = (float)cur;
            cur = bps[t * TAGS + cur];
        }
    }
}

// ---------------- launch ----------------------------------------------------------
extern "C" void kernel_launch(void* const* d_in, const int* in_sizes, int n_in,
                              void* d_out, int out_size)
{
    (void)in_sizes; (void)n_in;
    const int*   sent      = (const int*)  d_in[0];
    const float* h0        = (const float*)d_in[1];
    const float* c0        = (const float*)d_in[2];
    const float* embedding = (const float*)d_in[3];
    const float* w_ih_f    = (const float*)d_in[4];
    const float* w_hh_f    = (const float*)d_in[5];
    const float* b_f       = (const float*)d_in[6];
    const float* w_ih_b    = (const float*)d_in[7];
    const float* w_hh_b    = (const float*)d_in[8];
    const float* b_b       = (const float*)d_in[9];
    const float* lin_w     = (const float*)d_in[10];
    const float* lin_b     = (const float*)d_in[11];
    const float* trans     = (const float*)d_in[12];

    dim3 g1(SLEN / 16, 4, 2);
    k1_xg<<<g1, 256>>>(sent, embedding, w_ih_f, b_f, w_ih_b, b_b);
    k2_lstm<<<2 * CL, 256>>>(h0, c0, w_hh_f, w_hh_b);
    k3_feats<<<SLEN, 256>>>(lin_w, lin_b);

    cudaFuncSetAttribute(k4_viterbi, cudaFuncAttributeMaxDynamicSharedMemorySize,
                         SLEN * TAGS);
    k4_viterbi<<<1, 32, SLEN * TAGS>>>(trans, (float*)d_out, out_size);
}

// round 14
// speedup vs baseline: 1.1524x; 1.1524x over previous
#include <cuda_runtime.h>
#include <math.h>

#define SLEN 4096
#define EDIM 256
#define HDIM 256
#define TAGS 32
#define NEGV (-10000.0f)
#define CL 8            // CTAs per cluster (one cluster per direction)
#define STARTTAG 30
#define STOPTAG  31

// ---------------- scratch (device globals; no allocation allowed) ----------------
// xg reorganized: [dir][rank][t][128] -> each CTA's per-step slice is 512 B contiguous.
// pos within slice = gate*32 + (j & 31).
__device__ __align__(16) float g_xg[2][CL][SLEN][128];   // 32 MB
__device__ __align__(16) float g_hs[2][SLEN][HDIM];      // 8 MB hidden states
__device__ float g_feats[SLEN][TAGS];                    // 512 KB

// packed fp32x2 FMA (Blackwell FFMA2): d = a*b + c elementwise on float2
__device__ __forceinline__ float2 ffma2(float2 a, float2 b, float2 c) {
    float2 d;
    asm("fma.rn.f32x2 %0, %1, %2, %3;"
        : "=l"(*reinterpret_cast<unsigned long long*>(&d))
        : "l"(*reinterpret_cast<unsigned long long*>(&a)),
          "l"(*reinterpret_cast<unsigned long long*>(&b)),
          "l"(*reinterpret_cast<unsigned long long*>(&c)));
    return d;
}

// fast sigmoid/tanh via MUFU (__expf rel err ~1e-7: safe for argmax margins)
__device__ __forceinline__ float fast_sigmoid(float x) {
    float e = __expf(-x);
    return __fdividef(1.0f, 1.0f + e);
}
__device__ __forceinline__ float fast_tanh(float x) {
    float e = __expf(-2.0f * x);
    return __fdividef(1.0f - e, 1.0f + e);
}

// ---------------- K1: xg = emb . W_ih^T + b, written in CTA-sliced layout --------
__global__ void k1_xg(const int* __restrict__ sent,
                      const float* __restrict__ embedding,
                      const float* __restrict__ w_ih_f, const float* __restrict__ b_f,
                      const float* __restrict__ w_ih_b, const float* __restrict__ b_b)
{
    __shared__ __align__(16) float embs[16][EDIM];
    const int d  = blockIdx.z;
    const int t0 = blockIdx.x * 16;
    const int n  = blockIdx.y * 256 + threadIdx.x;   // gate row 0..1023
    const int gate = n >> 8;                         // 0..3
    const int j    = n & 255;                        // 0..255
    const int rank = j >> 5;                         // target CTA slice
    const int pos  = gate * 32 + (j & 31);           // slot within slice

    for (int tt = 0; tt < 16; tt++) {
        int posn = t0 + tt;
        int spos = d ? (SLEN - 1 - posn) : posn;
        int tok  = sent[spos];
        embs[tt][threadIdx.x] = embedding[(size_t)tok * EDIM + threadIdx.x];
    }
    __syncthreads();

    const float* W = d ? w_ih_b : w_ih_f;
    const float* B = d ? b_b    : b_f;
    float2 acc[16];
    float bias = B[n];
#pragma unroll
    for (int tt = 0; tt < 16; tt++) acc[tt] = make_float2(bias, 0.0f);

    const float4* Wr = (const float4*)(W + (size_t)n * EDIM);
#pragma unroll 4
    for (int e4 = 0; e4 < EDIM / 4; e4++) {
        float4 w4 = __ldg(&Wr[e4]);
        float2 wA = make_float2(w4.x, w4.y);
        float2 wB = make_float2(w4.z, w4.w);
#pragma unroll
        for (int tt = 0; tt < 16; tt++) {
            float4 ev = *(const float4*)&embs[tt][e4 * 4];
            acc[tt] = ffma2(wA, make_float2(ev.x, ev.y), acc[tt]);
            acc[tt] = ffma2(wB, make_float2(ev.z, ev.w), acc[tt]);
        }
    }
#pragma unroll
    for (int tt = 0; tt < 16; tt++)
        g_xg[d][rank][t0 + tt][pos] = acc[tt].x + acc[tt].y;
}

// ---------------- K2: clustered bidirectional LSTM recurrence --------------------
// R12 base + cp.async xg ring: warp 1 keeps an 8-slot 512 B ring of xg slices,
// 7 steps deep. Per step: warp1 wait_group 6 BEFORE the block sync (slot s
// guaranteed complete); issue step s+7 AFTER the sync (slot (s+7)&7 == (s-1)&7,
// readers provably done). xg consumption is an LDS. Warp 0 owns the mbarrier
// wait; one __syncthreads per step broadcasts both completions.
__global__ void __launch_bounds__(256, 1) __cluster_dims__(CL, 1, 1)
k2_lstm(const float* __restrict__ h0, const float* __restrict__ c0,
        const float* __restrict__ w_hh_f, const float* __restrict__ w_hh_b)
{
    __shared__ __align__(16) float hbuf[4][HDIM];   // 4-deep h ring (st.async filled)
    __shared__ __align__(16) float xbuf[8][128];    // xg ring, 512 B per slot
    __shared__ __align__(8) unsigned long long mbar[2];

    const int d = blockIdx.x >> 3;                  // cluster id = direction
    unsigned crank;
    asm("mov.u32 %0, %%cluster_ctarank;" : "=r"(crank));
    const int tid  = threadIdx.x;
    const int w    = tid >> 5;
    const int l    = tid & 31;
    const int a    = l >> 3;                        // j slot within warp
    const int gate = (l >> 1) & 3;                  // i,f,g,o
    const int half = l & 1;                         // column half (interleaved)
    const int jl   = w * 4 + a;                     // 0..31
    const int j    = (int)crank * 32 + jl;          // global h index
    const int j0   = (int)crank * 32 + w * 4;       // warp's first j
    const int grow = gate * HDIM + j;               // gate row in [0,1024)
    const int xidx = gate * 32 + jl;                // xg slot index for this thread

    const float* W = d ? w_hh_b : w_hh_f;
    float4 wr[32];                                  // 128 weights / thread
#pragma unroll
    for (int m = 0; m < 32; m++)
        wr[m] = *(const float4*)(W + (size_t)grow * HDIM + (size_t)(m * 2 + half) * 4);

    unsigned hb = (unsigned)__cvta_generic_to_shared(&hbuf[0][0]);
    unsigned mb = (unsigned)__cvta_generic_to_shared(&mbar[0]);
    unsigned xb = (unsigned)__cvta_generic_to_shared(&xbuf[0][0]);
    // per-lane scalar remote addresses: this lane's send target is CTA (l & 7)
    unsigned r_h, r_m;
    {
        unsigned myc = (unsigned)(l & 7);
        asm("mapa.shared::cluster.u32 %0, %1, %2;" : "=r"(r_h) : "r"(hb), "r"(myc));
        asm("mapa.shared::cluster.u32 %0, %1, %2;" : "=r"(r_m) : "r"(mb), "r"(myc));
    }
    const float* xrow = &g_xg[d][crank][0][0];      // row stride 128 floats

    if (tid == 0) {
        asm volatile("mbarrier.init.shared.b64 [%0], %1;" :: "r"(mb),     "r"(1) : "memory");
        asm volatile("mbarrier.init.shared.b64 [%0], %1;" :: "r"(mb + 8), "r"(1) : "memory");
        // pre-post: h_1 arrives on mbar[1], h_2 on mbar[0]; 1024 B each
        asm volatile("mbarrier.arrive.expect_tx.shared.b64 _, [%0], %1;"
                     :: "r"(mb + 8), "r"(HDIM * 4) : "memory");
        asm volatile("mbarrier.arrive.expect_tx.shared.b64 _, [%0], %1;"
                     :: "r"(mb),     "r"(HDIM * 4) : "memory");
    }
    hbuf[0][tid] = h0[d * HDIM + tid];              // step 1 reads hbuf[0] = h0

    // xg ring prolog: warp 1 issues steps 1..7 (slots 1..7), one group each
    if (w == 1) {
#pragma unroll
        for (int sp = 1; sp <= 7; sp++) {
            unsigned dst = xb + (unsigned)(((sp & 7) * 128 + l * 4) * 4);
            const float* src = xrow + (size_t)(sp - 1) * 128 + l * 4;
            asm volatile("cp.async.ca.shared.global [%0], [%1], 16;"
                         :: "r"(dst), "l"(src) : "memory");
            asm volatile("cp.async.commit_group;" ::: "memory");
        }
    }
    __syncthreads();
    // all CTAs' mbarrier init done before any st.async can target them
    asm volatile("barrier.cluster.arrive.aligned;" ::: "memory");
    asm volatile("barrier.cluster.wait.aligned;"   ::: "memory");

    const bool prod = ((l & 7) == 0);               // lanes 0,8,16,24: own a j
    float cst = c0[d * HDIM + j];                   // used only on prod lanes

    for (int s = 1; s <= SLEN; s++) {
        const int t = s - 1;

        if (w == 0 && s > 1) {                      // ONE warp on the mbarrier word
            unsigned mbw = mb + (unsigned)((s - 1) & 1) * 8u;
            unsigned par = (unsigned)(((s - 2) >> 1) & 1);
            unsigned done;
            asm volatile(
                "{\n\t.reg .pred p;\n\t"
                "mbarrier.try_wait.parity.acquire.cluster.shared::cta.b64 p, [%1], %2, 0x989680;\n\t"
                "selp.b32 %0, 1, 0, p;\n\t}"
                : "=r"(done) : "r"(mbw), "r"(par) : "memory");
            while (!done) {
                asm volatile(
                    "{\n\t.reg .pred p;\n\t"
                    "mbarrier.try_wait.parity.acquire.cluster.shared::cta.b64 p, [%1], %2, 0x989680;\n\t"
                    "selp.b32 %0, 1, 0, p;\n\t}"
                    : "=r"(done) : "r"(mbw), "r"(par) : "memory");
            }
            // this barrier's next phase handles h_{s+1}: re-arm it now
            if (l == 0 && s + 1 <= SLEN)
                asm volatile("mbarrier.arrive.expect_tx.shared.b64 _, [%0], %1;"
                             :: "r"(mbw), "r"(HDIM * 4) : "memory");
        }
        if (w == 1) {                               // slot s complete (pending <= 6)
            asm volatile("cp.async.wait_group 6;" ::: "memory");
        }
        __syncthreads();                            // h + xbuf visible to all warps

        // issue xg for step s+7 (slot (s+7)&7 == (s-1)&7; its readers are done)
        if (w == 1) {
            int sp = s + 7;
            int row = (sp <= SLEN) ? (sp - 1) : (SLEN - 1);   // clamped dummy at tail
            unsigned dst = xb + (unsigned)(((sp & 7) * 128 + l * 4) * 4);
            const float* src = xrow + (size_t)row * 128 + l * 4;
            asm volatile("cp.async.ca.shared.global [%0], [%1], 16;"
                         :: "r"(dst), "l"(src) : "memory");
            asm volatile("cp.async.commit_group;" ::: "memory");
        }

        const float xw = xbuf[s & 7][xidx];         // LDS, latency-trivial

        const float* hsm = &hbuf[(s - 1) & 3][0];
        float2 acc[4];
#pragma unroll
        for (int k = 0; k < 4; k++) acc[k] = make_float2(0.0f, 0.0f);
#pragma unroll
        for (int m = 0; m < 32; m++) {
            float4 h4 = *(const float4*)(hsm + (m * 2 + half) * 4);
            float4 w4 = wr[m];
            float2 ac = acc[m & 3];
            ac = ffma2(make_float2(w4.x, w4.y), make_float2(h4.x, h4.y), ac);
            ac = ffma2(make_float2(w4.z, w4.w), make_float2(h4.z, h4.w), ac);
            acc[m & 3] = ac;
        }
        float accS = ((acc[0].x + acc[0].y) + (acc[1].x + acc[1].y))
                   + ((acc[2].x + acc[2].y) + (acc[3].x + acc[3].y));
        accS += __shfl_xor_sync(0xffffffffu, accS, 1);   // combine halves

        float av  = accS + xw;
        float val = (gate == 2) ? fast_tanh(av) : fast_sigmoid(av);

        const int base = l & 24;                    // lane group of this j
        float iv = __shfl_sync(0xffffffffu, val, base + 0);
        float fv = __shfl_sync(0xffffffffu, val, base + 2);
        float gv = __shfl_sync(0xffffffffu, val, base + 4);
        float ov = __shfl_sync(0xffffffffu, val, base + 6);

        float hv = 0.0f;
        if (prod) {
            cst = fmaf(fv, cst, iv * gv);
            hv  = ov * fast_tanh(cst);
        }
        // gather warp's 4 h-values to all lanes; lanes 0..7 send to CTA c = l
        float h0v = __shfl_sync(0xffffffffu, hv, 0);
        float h1v = __shfl_sync(0xffffffffu, hv, 8);
        float h2v = __shfl_sync(0xffffffffu, hv, 16);
        float h3v = __shfl_sync(0xffffffffu, hv, 24);

        if (l < CL) {
            unsigned dst  = r_h + (unsigned)(((s & 3) * HDIM + j0) * 4);
            unsigned mdst = r_m + (unsigned)((s & 1) * 8);
            asm volatile(
                "st.async.weak.shared::cluster.mbarrier::complete_tx::bytes.v4.b32 "
                "[%0], {%1, %2, %3, %4}, [%5];"
                :: "r"(dst),
                   "r"(__float_as_uint(h0v)), "r"(__float_as_uint(h1v)),
                   "r"(__float_as_uint(h2v)), "r"(__float_as_uint(h3v)),
                   "r"(mdst) : "memory");
        }
        if (l == 0)
            __stcg((float4*)&g_hs[d][t][j0], make_float4(h0v, h1v, h2v, h3v));
    }

    // no CTA may exit while peers still write into its SMEM
    asm volatile("barrier.cluster.arrive.aligned;" ::: "memory");
    asm volatile("barrier.cluster.wait.aligned;"   ::: "memory");
}

// ---------------- K3: feats[t] = [hs_f[t], hs_b[S-1-t]] @ lin_w^T + lin_b --------
__global__ void k3_feats(const float* __restrict__ lin_w, const float* __restrict__ lin_b)
{
    __shared__ __align__(16) float cat[2 * HDIM];
    const int t   = blockIdx.x;
    const int tid = threadIdx.x;                // 256
    cat[tid]        = g_hs[0][t][tid];
    cat[HDIM + tid] = g_hs[1][SLEN - 1 - t][tid];
    __syncthreads();

    const int n = tid >> 3, seg = tid & 7;
    const float* w  = lin_w + (size_t)n * 2 * HDIM + seg * 64;
    const float* cc = cat + seg * 64;
    float s = 0.0f;
#pragma unroll 16
    for (int k = 0; k < 64; k++) s = fmaf(w[k], cc[k], s);
    s += __shfl_xor_sync(0xffffffffu, s, 1);
    s += __shfl_xor_sync(0xffffffffu, s, 2);
    s += __shfl_xor_sync(0xffffffffu, s, 4);
    if (seg == 0) g_feats[t][n] = s + lin_b[n];
}

// ---------------- K4: single-warp Viterbi + backtrack (bps in SMEM) --------------
__global__ void __launch_bounds__(32, 1) k4_viterbi(
    const float* __restrict__ trans, float* __restrict__ out, int out_size)
{
    extern __shared__ unsigned char bps[];      // SLEN*TAGS bytes = 128 KB
    const int lane = threadIdx.x;

    float trn[TAGS];
#pragma unroll
    for (int p = 0; p < TAGS; p++) trn[p] = __ldg(&trans[lane * TAGS + p]);
    const float stop_tr = __ldg(&trans[STOPTAG * TAGS + lane]);

    float fv  = (lane == STARTTAG) ? 0.0f : NEGV;
    float ftc = g_feats[0][lane];
    float ftn = g_feats[1][lane];

    for (int t = 0; t < SLEN; t++) {
        float v[TAGS];
        int   bi[TAGS];
#pragma unroll
        for (int p = 0; p < TAGS; p++) {
            v[p]  = __shfl_sync(0xffffffffu, fv, p) + trn[p];
            bi[p] = p;
        }
        // first-max tree: strict > keeps the lower index on ties (== jnp.argmax)
#pragma unroll
        for (int s = 1; s < TAGS; s <<= 1) {
#pragma unroll
            for (int k = 0; k < TAGS; k += 2 * s) {
                if (v[k + s] > v[k]) { v[k] = v[k + s]; bi[k] = bi[k + s]; }
            }
        }
        bps[t * TAGS + lane] = (unsigned char)bi[0];
        fv  = v[0] + ftc;
        ftc = ftn;
        ftn = (t + 2 < SLEN) ? g_feats[t + 2][lane] : 0.0f;
    }

    float v = fv + stop_tr;
    int   b = lane;
#pragma unroll
    for (int ofs = 16; ofs > 0; ofs >>= 1) {
        float ov = __shfl_down_sync(0xffffffffu, v, ofs);
        int   oi = __shfl_down_sync(0xffffffffu, b, ofs);
        if (ov > v || (ov == v && oi < b)) { v = ov; b = oi; }
    }

    if (lane == 0) {
        const int off = (out_size > SLEN) ? 1 : 0;
        if (off) out[0] = v;
        int cur = b;
        for (int t = SLEN - 1; t >= 0; t--) {
            int idx = off + t;
            if (idx < out_size) out[idx] = (float)cur;
            cur = bps[t * TAGS + cur];
        }
    }
}

// ---------------- launch ----------------------------------------------------------
extern "C" void kernel_launch(void* const* d_in, const int* in_sizes, int n_in,
                              void* d_out, int out_size)
{
    (void)in_sizes; (void)n_in;
    const int*   sent      = (const int*)  d_in[0];
    const float* h0        = (const float*)d_in[1];
    const float* c0        = (const float*)d_in[2];
    const float* embedding = (const float*)d_in[3];
    const float* w_ih_f    = (const float*)d_in[4];
    const float* w_hh_f    = (const float*)d_in[5];
    const float* b_f       = (const float*)d_in[6];
    const float* w_ih_b    = (const float*)d_in[7];
    const float* w_hh_b    = (const float*)d_in[8];
    const float* b_b       = (const float*)d_in[9];
    const float* lin_w     = (const float*)d_in[10];
    const float* lin_b     = (const float*)d_in[11];
    const float* trans     = (const float*)d_in[12];

    dim3 g1(SLEN / 16, 4, 2);
    k1_xg<<<g1, 256>>>(sent, embedding, w_ih_f, b_f, w_ih_b, b_b);
    k2_lstm<<<2 * CL, 256>>>(h0, c0, w_hh_f, w_hh_b);
    k3_feats<<<SLEN, 256>>>(lin_w, lin_b);

    cudaFuncSetAttribute(k4_viterbi, cudaFuncAttributeMaxDynamicSharedMemorySize,
                         SLEN * TAGS);
    k4_viterbi<<<1, 32, SLEN * TAGS>>>(trans, (float*)d_out, out_size);
}

// round 16
// speedup vs baseline: 1.1868x; 1.0299x over previous
#include <cuda_runtime.h>
#include <math.h>

#define SLEN 4096
#define EDIM 256
#define HDIM 256
#define TAGS 32
#define NEGV (-10000.0f)
#define CL 8            // CTAs per cluster (one cluster per direction)
#define STARTTAG 30
#define STOPTAG  31
#define NWORK (4 * 2 * (SLEN / 16))     // 2048 k1 worker CTAs
#define PAD_SMEM (120 * 1024)           // 1 CTA/SM everywhere (unused reservation)

// ---------------- scratch (device globals; no allocation allowed) ----------------
// xg: [dir][rank][t][128] -> each CTA's per-step slice is 512 B contiguous.
__device__ __align__(16) float g_xg[2][CL][SLEN][128];   // 32 MB
__device__ __align__(16) float g_hs[2][SLEN][HDIM];      // 8 MB hidden states
__device__ float g_feats[SLEN][TAGS];                    // 512 KB
__device__ int   g_row_cnt[2][SLEN / 16];                // xg chunk readiness (target 4)

// packed fp32x2 FMA (Blackwell FFMA2)
__device__ __forceinline__ float2 ffma2(float2 a, float2 b, float2 c) {
    float2 d;
    asm("fma.rn.f32x2 %0, %1, %2, %3;"
        : "=l"(*reinterpret_cast<unsigned long long*>(&d))
        : "l"(*reinterpret_cast<unsigned long long*>(&a)),
          "l"(*reinterpret_cast<unsigned long long*>(&b)),
          "l"(*reinterpret_cast<unsigned long long*>(&c)));
    return d;
}

__device__ __forceinline__ float fast_sigmoid(float x) {
    float e = __expf(-x);
    return __fdividef(1.0f, 1.0f + e);
}
__device__ __forceinline__ float fast_tanh(float x) {
    float e = __expf(-2.0f * x);
    return __fdividef(1.0f - e, 1.0f + e);
}

// ---------------- fused kernel: bids 0..15 = LSTM clusters, 16.. = xg workers ----
__global__ void __launch_bounds__(256, 1) __cluster_dims__(CL, 1, 1)
k2_fused(const int* __restrict__ sent,
         const float* __restrict__ embedding,
         const float* __restrict__ w_ih_f, const float* __restrict__ b_f,
         const float* __restrict__ w_ih_b, const float* __restrict__ b_b,
         const float* __restrict__ h0, const float* __restrict__ c0,
         const float* __restrict__ w_hh_f, const float* __restrict__ w_hh_b)
{
    // ---------------- shared state (both paths; 1 CTA/SM via PAD_SMEM) ----------
    __shared__ __align__(16) float embs[16][EDIM];  // k1 worker staging (16 KB)
    __shared__ __align__(16) float hbuf[4][HDIM];   // k2: 4-deep h ring (st.async)
    __shared__ __align__(16) float xbuf[8][128];    // k2: xg ring, 512 B per slot
    __shared__ __align__(8) unsigned long long mbar[2];

    const int tid = threadIdx.x;

    // ========================= k1 WORKER PATH ====================================
    if (blockIdx.x >= 2 * CL) {
        const int Wk = blockIdx.x - 2 * CL;         // 0..NWORK-1
        const int qx = Wk & 3;                      // gate-row quarter
        const int d  = (Wk >> 2) & 1;               // direction
        const int z  = Wk >> 3;                     // t-chunk 0..255 (slowest)
        const int t0 = z * 16;
        const int n  = qx * 256 + tid;              // gate row 0..1023
        const int gate = n >> 8;
        const int j    = n & 255;
        const int rank = j >> 5;
        const int pos  = gate * 32 + (j & 31);

        for (int tt = 0; tt < 16; tt++) {
            int posn = t0 + tt;
            int spos = d ? (SLEN - 1 - posn) : posn;
            int tok  = sent[spos];
            embs[tt][tid] = embedding[(size_t)tok * EDIM + tid];
        }
        __syncthreads();

        const float* Wih = d ? w_ih_b : w_ih_f;
        const float* B   = d ? b_b    : b_f;
        float2 acc[16];
        float bias = B[n];
#pragma unroll
        for (int tt = 0; tt < 16; tt++) acc[tt] = make_float2(bias, 0.0f);

        const float4* Wr = (const float4*)(Wih + (size_t)n * EDIM);
#pragma unroll 4
        for (int e4 = 0; e4 < EDIM / 4; e4++) {
            float4 w4 = __ldg(&Wr[e4]);
            float2 wA = make_float2(w4.x, w4.y);
            float2 wB = make_float2(w4.z, w4.w);
#pragma unroll
            for (int tt = 0; tt < 16; tt++) {
                float4 ev = *(const float4*)&embs[tt][e4 * 4];
                acc[tt] = ffma2(wA, make_float2(ev.x, ev.y), acc[tt]);
                acc[tt] = ffma2(wB, make_float2(ev.z, ev.w), acc[tt]);
            }
        }
#pragma unroll
        for (int tt = 0; tt < 16; tt++)
            g_xg[d][rank][t0 + tt][pos] = acc[tt].x + acc[tt].y;

        __syncthreads();                            // all block stores hb-ordered
        if (tid == 0)
            asm volatile("red.release.gpu.add.u32 [%0], 1;"
                         :: "l"(&g_row_cnt[d][z]) : "memory");
        return;
    }

    // ========================= k2 LSTM PATH ======================================
    const int d = blockIdx.x >> 3;                  // cluster id = direction
    unsigned crank;
    asm("mov.u32 %0, %%cluster_ctarank;" : "=r"(crank));
    const int w    = tid >> 5;
    const int l    = tid & 31;
    const int a    = l >> 3;
    const int gate = (l >> 1) & 3;
    const int half = l & 1;
    const int jl   = w * 4 + a;
    const int j    = (int)crank * 32 + jl;
    const int j0   = (int)crank * 32 + w * 4;
    const int grow = gate * HDIM + j;
    const int xidx = gate * 32 + jl;

    const float* W = d ? w_hh_b : w_hh_f;
    float4 wr[32];
#pragma unroll
    for (int m = 0; m < 32; m++)
        wr[m] = *(const float4*)(W + (size_t)grow * HDIM + (size_t)(m * 2 + half) * 4);

    unsigned hb = (unsigned)__cvta_generic_to_shared(&hbuf[0][0]);
    unsigned mb = (unsigned)__cvta_generic_to_shared(&mbar[0]);
    unsigned xb = (unsigned)__cvta_generic_to_shared(&xbuf[0][0]);
    unsigned r_h, r_m;
    {
        unsigned myc = (unsigned)(l & 7);
        asm("mapa.shared::cluster.u32 %0, %1, %2;" : "=r"(r_h) : "r"(hb), "r"(myc));
        asm("mapa.shared::cluster.u32 %0, %1, %2;" : "=r"(r_m) : "r"(mb), "r"(myc));
    }
    const float* xrow = &g_xg[d][crank][0][0];      // row stride 128 floats
    const int*   cnt  = &g_row_cnt[d][0];

    if (tid == 0) {
        asm volatile("mbarrier.init.shared.b64 [%0], %1;" :: "r"(mb),     "r"(1) : "memory");
        asm volatile("mbarrier.init.shared.b64 [%0], %1;" :: "r"(mb + 8), "r"(1) : "memory");
        asm volatile("mbarrier.arrive.expect_tx.shared.b64 _, [%0], %1;"
                     :: "r"(mb + 8), "r"(HDIM * 4) : "memory");
        asm volatile("mbarrier.arrive.expect_tx.shared.b64 _, [%0], %1;"
                     :: "r"(mb),     "r"(HDIM * 4) : "memory");
    }
    hbuf[0][tid] = h0[d * HDIM + tid];              // step 1 reads hbuf[0] = h0

    int got = -1;                                   // warp1: highest ready chunk
    // xg ring prolog: rows 0..6 live in chunk 0 — wait for it, then issue
    if (w == 1) {
        if (l == 0) {
            int v;
            do { asm volatile("ld.acquire.gpu.u32 %0, [%1];"
                              : "=r"(v) : "l"(cnt + 0) : "memory"); } while (v < 4);
        }
        __syncwarp();
        got = 0;
#pragma unroll
        for (int sp = 1; sp <= 7; sp++) {
            unsigned dst = xb + (unsigned)(((sp & 7) * 128 + l * 4) * 4);
            const float* src = xrow + (size_t)(sp - 1) * 128 + l * 4;
            asm volatile("cp.async.ca.shared.global [%0], [%1], 16;"
                         :: "r"(dst), "l"(src) : "memory");
            asm volatile("cp.async.commit_group;" ::: "memory");
        }
    }
    __syncthreads();
    asm volatile("barrier.cluster.arrive.aligned;" ::: "memory");
    asm volatile("barrier.cluster.wait.aligned;"   ::: "memory");

    const bool prod = ((l & 7) == 0);
    float cst = c0[d * HDIM + j];

    for (int s = 1; s <= SLEN; s++) {
        const int t = s - 1;

        if (w == 0 && s > 1) {                      // ONE warp on the mbarrier word
            unsigned mbw = mb + (unsigned)((s - 1) & 1) * 8u;
            unsigned par = (unsigned)(((s - 2) >> 1) & 1);
            unsigned done;
            asm volatile(
                "{\n\t.reg .pred p;\n\t"
                "mbarrier.try_wait.parity.acquire.cluster.shared::cta.b64 p, [%1], %2, 0x989680;\n\t"
                "selp.b32 %0, 1, 0, p;\n\t}"
                : "=r"(done) : "r"(mbw), "r"(par) : "memory");
            while (!done) {
                asm volatile(
                    "{\n\t.reg .pred p;\n\t"
                    "mbarrier.try_wait.parity.acquire.cluster.shared::cta.b64 p, [%1], %2, 0x989680;\n\t"
                    "selp.b32 %0, 1, 0, p;\n\t}"
                    : "=r"(done) : "r"(mbw), "r"(par) : "memory");
            }
            if (l == 0 && s + 1 <= SLEN)
                asm volatile("mbarrier.arrive.expect_tx.shared.b64 _, [%0], %1;"
                             :: "r"(mbw), "r"(HDIM * 4) : "memory");
        }
        if (w == 1) {                               // slot s complete (pending <= 6)
            asm volatile("cp.async.wait_group 6;" ::: "memory");
        }
        __syncthreads();                            // h + xbuf visible to all warps

        // issue xg for step s+7 (slot (s+7)&7 == (s-1)&7; its readers are done)
        if (w == 1) {
            int sp = s + 7;
            int row = (sp <= SLEN) ? (sp - 1) : (SLEN - 1);
            int chunk = row >> 4;
            if (chunk > got) {                      // gate on worker chunk readiness
                if (l == 0) {
                    int v;
                    do { asm volatile("ld.acquire.gpu.u32 %0, [%1];"
                                      : "=r"(v) : "l"(cnt + chunk) : "memory"); } while (v < 4);
                }
                __syncwarp();
                got = chunk;
            }
            unsigned dst = xb + (unsigned)(((sp & 7) * 128 + l * 4) * 4);
            const float* src = xrow + (size_t)row * 128 + l * 4;
            asm volatile("cp.async.ca.shared.global [%0], [%1], 16;"
                         :: "r"(dst), "l"(src) : "memory");
            asm volatile("cp.async.commit_group;" ::: "memory");
        }

        const float xw = xbuf[s & 7][xidx];         // LDS, latency-trivial

        const float* hsm = &hbuf[(s - 1) & 3][0];
        float2 acc[4];
#pragma unroll
        for (int k = 0; k < 4; k++) acc[k] = make_float2(0.0f, 0.0f);
#pragma unroll
        for (int m = 0; m < 32; m++) {
            float4 h4 = *(const float4*)(hsm + (m * 2 + half) * 4);
            float4 w4 = wr[m];
            float2 ac = acc[m & 3];
            ac = ffma2(make_float2(w4.x, w4.y), make_float2(h4.x, h4.y), ac);
            ac = ffma2(make_float2(w4.z, w4.w), make_float2(h4.z, h4.w), ac);
            acc[m & 3] = ac;
        }
        float accS = ((acc[0].x + acc[0].y) + (acc[1].x + acc[1].y))
                   + ((acc[2].x + acc[2].y) + (acc[3].x + acc[3].y));
        accS += __shfl_xor_sync(0xffffffffu, accS, 1);

        float av  = accS + xw;
        float val = (gate == 2) ? fast_tanh(av) : fast_sigmoid(av);

        const int base = l & 24;
        float iv = __shfl_sync(0xffffffffu, val, base + 0);
        float fv = __shfl_sync(0xffffffffu, val, base + 2);
        float gv = __shfl_sync(0xffffffffu, val, base + 4);
        float ov = __shfl_sync(0xffffffffu, val, base + 6);

        float hv = 0.0f;
        if (prod) {
            cst = fmaf(fv, cst, iv * gv);
            hv  = ov * fast_tanh(cst);
        }
        float h0v = __shfl_sync(0xffffffffu, hv, 0);
        float h1v = __shfl_sync(0xffffffffu, hv, 8);
        float h2v = __shfl_sync(0xffffffffu, hv, 16);
        float h3v = __shfl_sync(0xffffffffu, hv, 24);

        if (l < CL) {
            unsigned dst  = r_h + (unsigned)(((s & 3) * HDIM + j0) * 4);
            unsigned mdst = r_m + (unsigned)((s & 1) * 8);
            asm volatile(
                "st.async.weak.shared::cluster.mbarrier::complete_tx::bytes.v4.b32 "
                "[%0], {%1, %2, %3, %4}, [%5];"
                :: "r"(dst),
                   "r"(__float_as_uint(h0v)), "r"(__float_as_uint(h1v)),
                   "r"(__float_as_uint(h2v)), "r"(__float_as_uint(h3v)),
                   "r"(mdst) : "memory");
        }
        if (l == 0)
            __stcg((float4*)&g_hs[d][t][j0], make_float4(h0v, h1v, h2v, h3v));
    }

    asm volatile("barrier.cluster.arrive.aligned;" ::: "memory");
    asm volatile("barrier.cluster.wait.aligned;"   ::: "memory");
}

// ---------------- K3: feats[t] = [hs_f[t], hs_b[S-1-t]] @ lin_w^T + lin_b --------
__global__ void k3_feats(const float* __restrict__ lin_w, const float* __restrict__ lin_b)
{
    __shared__ __align__(16) float cat[2 * HDIM];
    const int t   = blockIdx.x;
    const int tid = threadIdx.x;                // 256
    cat[tid]        = g_hs[0][t][tid];
    cat[HDIM + tid] = g_hs[1][SLEN - 1 - t][tid];
    __syncthreads();

    const int n = tid >> 3, seg = tid & 7;
    const float* w  = lin_w + (size_t)n * 2 * HDIM + seg * 64;
    const float* cc = cat + seg * 64;
    float s = 0.0f;
#pragma unroll 16
    for (int k = 0; k < 64; k++) s = fmaf(w[k], cc[k], s);
    s += __shfl_xor_sync(0xffffffffu, s, 1);
    s += __shfl_xor_sync(0xffffffffu, s, 2);
    s += __shfl_xor_sync(0xffffffffu, s, 4);
    if (seg == 0) g_feats[t][n] = s + lin_b[n];
}

// ---------------- K4: single-warp Viterbi + backtrack (bps in SMEM) --------------
__global__ void __launch_bounds__(32, 1) k4_viterbi(
    const float* __restrict__ trans, float* __restrict__ out, int out_size)
{
    extern __shared__ unsigned char bps[];      // SLEN*TAGS bytes = 128 KB
    const int lane = threadIdx.x;

    float trn[TAGS];
#pragma unroll
    for (int p = 0; p < TAGS; p++) trn[p] = __ldg(&trans[lane * TAGS + p]);
    const float stop_tr = __ldg(&trans[STOPTAG * TAGS + lane]);

    float fv  = (lane == STARTTAG) ? 0.0f : NEGV;
    float ftc = g_feats[0][lane];
    float ftn = g_feats[1][lane];

    for (int t = 0; t < SLEN; t++) {
        float v[TAGS];
        int   bi[TAGS];
#pragma unroll
        for (int p = 0; p < TAGS; p++) {
            v[p]  = __shfl_sync(0xffffffffu, fv, p) + trn[p];
            bi[p] = p;
        }
#pragma unroll
        for (int s = 1; s < TAGS; s <<= 1) {
#pragma unroll
            for (int k = 0; k < TAGS; k += 2 * s) {
                if (v[k + s] > v[k]) { v[k] = v[k + s]; bi[k] = bi[k + s]; }
            }
        }
        bps[t * TAGS + lane] = (unsigned char)bi[0];
        fv  = v[0] + ftc;
        ftc = ftn;
        ftn = (t + 2 < SLEN) ? g_feats[t + 2][lane] : 0.0f;
    }

    float v = fv + stop_tr;
    int   b = lane;
#pragma unroll
    for (int ofs = 16; ofs > 0; ofs >>= 1) {
        float ov = __shfl_down_sync(0xffffffffu, v, ofs);
        int   oi = __shfl_down_sync(0xffffffffu, b, ofs);
        if (ov > v || (ov == v && oi < b)) { v = ov; b = oi; }
    }

    if (lane == 0) {
        const int off = (out_size > SLEN) ? 1 : 0;
        if (off) out[0] = v;
        int cur = b;
        for (int t = SLEN - 1; t >= 0; t--) {
            int idx = off + t;
            if (idx < out_size) out[idx] = (float)cur;
            cur = bps[t * TAGS + cur];
        }
    }
}

// ---------------- launch ----------------------------------------------------------
extern "C" void kernel_launch(void* const* d_in, const int* in_sizes, int n_in,
                              void* d_out, int out_size)
{
    (void)in_sizes; (void)n_in;
    const int*   sent      = (const int*)  d_in[0];
    const float* h0        = (const float*)d_in[1];
    const float* c0        = (const float*)d_in[2];
    const float* embedding = (const float*)d_in[3];
    const float* w_ih_f    = (const float*)d_in[4];
    const float* w_hh_f    = (const float*)d_in[5];
    const float* b_f       = (const float*)d_in[6];
    const float* w_ih_b    = (const float*)d_in[7];
    const float* w_hh_b    = (const float*)d_in[8];
    const float* b_b       = (const float*)d_in[9];
    const float* lin_w     = (const float*)d_in[10];
    const float* lin_b     = (const float*)d_in[11];
    const float* trans     = (const float*)d_in[12];

    // zero the xg chunk-readiness flags (in-graph, runs every replay)
    void* cntp = nullptr;
    cudaGetSymbolAddress(&cntp, g_row_cnt);
    cudaMemsetAsync(cntp, 0, sizeof(int) * 2 * (SLEN / 16), 0);

    // ONE fused launch: 16 LSTM cluster CTAs (wave-1 resident) + 2048 xg workers.
    // PAD_SMEM forces 1 CTA/SM so workers never share an SM with LSTM CTAs.
    cudaFuncSetAttribute(k2_fused, cudaFuncAttributeMaxDynamicSharedMemorySize,
                         PAD_SMEM);
    k2_fused<<<2 * CL + NWORK, 256, PAD_SMEM>>>(sent, embedding,
                                                w_ih_f, b_f, w_ih_b, b_b,
                                                h0, c0, w_hh_f, w_hh_b);

    k3_feats<<<SLEN, 256>>>(lin_w, lin_b);

    cudaFuncSetAttribute(k4_viterbi, cudaFuncAttributeMaxDynamicSharedMemorySize,
                         SLEN * TAGS);
    k4_viterbi<<<1, 32, SLEN * TAGS>>>(trans, (float*)d_out, out_size);
}